// round 1
// baseline (speedup 1.0000x reference)
#include <cuda_runtime.h>
#include <math.h>
#include <stdint.h>

#define NN 4096
#define DD 256
#define HH 4
#define DHH 64
#define EE 65536
#define NW 128          // 4096 bits / 32
#define LNEPS 1e-5f

// ---------------- device scratch (static, no allocs) ----------------
__device__ int      g_is64;
__device__ unsigned g_A  [NN*NW];
__device__ unsigned g_ML [NN*NW];
__device__ unsigned g_UND[NN*NW];
__device__ unsigned g_MM [NN*NW];

__device__ float g_z   [3*HH*NN*DD];   // 48 MB  z[sc][h][n][d]
__device__ float g_ssrc[3*HH*NN];
__device__ float g_F1  [3*HH*NN];      // exp(ssrc)
__device__ float g_F2  [3*HH*NN];      // exp(0.2 ssrc)
__device__ float g_T   [3*HH*NN];      // -sdst
__device__ float g_E1  [3*HH*NN];      // exp(sdst)
__device__ float g_E2  [3*HH*NN];      // exp(0.2 sdst)

__device__ float g_cat [NN*3*DD];      // [x_local | x_mid | x_global] row-major, ld=768
__device__ float g_sorted[HH*NN];
__device__ int   g_perm  [HH*NN];
__device__ float g_P1[HH*NN*DD];       // inclusive prefix of F1*z along sorted order
__device__ float g_P2[HH*NN*DD];
__device__ float g_C1[HH*NN];
__device__ float g_C2[HH*NN];

__device__ float g_q   [NN*DD];
__device__ float g_k3  [3*NN*DD];
__device__ float g_v3  [3*NN*DD];
__device__ float g_att [NN*DD];
__device__ float g_xatt[NN*DD];
__device__ float g_hbuf[NN*DD];

// ---------------- small utility kernels ----------------
__global__ void k_detect(const unsigned* e) {
    if (threadIdx.x == 0) {
        int all0 = 1;
        for (int i = 0; i < 128; i++) if (e[2*i+1] != 0u) { all0 = 0; break; }
        g_is64 = all0;   // int64 little-endian: high words of values < 4096 are 0
    }
}

__global__ void k_clear() {
    int i = blockIdx.x * blockDim.x + threadIdx.x;
    if (i < NN*NW) { g_A[i]=0u; g_ML[i]=0u; g_UND[i]=0u; g_MM[i]=0u; }
}

__global__ void k_edges(const int* e) {
    int i = blockIdx.x * blockDim.x + threadIdx.x;
    if (i >= EE) return;
    int s, t;
    if (g_is64) { s = e[2*i]; t = e[2*(EE+i)]; }
    else        { s = e[i];   t = e[EE+i];     }
    atomicOr(&g_A [s*NW + (t>>5)], 1u << (t & 31));   // A[s][t]
    atomicOr(&g_ML[t*NW + (s>>5)], 1u << (s & 31));   // M_local[t][s] = A^T
}

__global__ void k_eye_ml() {
    int i = blockIdx.x * blockDim.x + threadIdx.x;
    if (i < NN) g_ML[i*NW + (i>>5)] |= 1u << (i & 31);
}

// und[i] = A[i] | OR_{k in out(i)} A[k]   (1-hop | 2-hop)
__global__ void k_twohop() {
    int i = blockIdx.x, w = threadIdx.x;   // 128 threads
    __shared__ unsigned sh[NW];
    sh[w] = g_A[i*NW + w];
    __syncthreads();
    unsigned acc = sh[w];
    for (int w2 = 0; w2 < NW; w2++) {
        unsigned bits = sh[w2];
        while (bits) {
            int b = __ffs(bits) - 1; bits &= bits - 1;
            acc |= g_A[((w2<<5)+b)*NW + w];
        }
    }
    g_UND[i*NW + w] = acc;
}

// MM[i][j] = und[i][j] | und[j][i] | (i==j)
__global__ void k_mm() {
    int i = blockIdx.x, w = threadIdx.x;   // 128 threads
    unsigned res = g_UND[i*NW + w];
    int iw = i >> 5; unsigned ib = (unsigned)(i & 31);
    for (int b = 0; b < 32; b++) {
        int j = (w << 5) + b;
        res |= ((g_UND[j*NW + iw] >> ib) & 1u) << b;
    }
    if (w == iw) res |= 1u << ib;
    g_MM[i*NW + w] = res;
}

// ---------------- generic C[M,256] = A[M,K] @ B[256,K]^T (+bias) ----------------
// B row-major with ldb=K (PyTorch-style weight). 64x64 tile, BK=16, 256 threads, 4x4/thread.
__global__ void k_gemm(const float* __restrict__ A, int lda, long sA,
                       const float* __restrict__ B, long sB,
                       const float* __restrict__ bias,
                       float* __restrict__ C, int ldc, long sC, int K) {
    int bz = blockIdx.z;
    A += (long)bz * sA; B += (long)bz * sB; C += (long)bz * sC;
    int bm = blockIdx.y << 6, bn = blockIdx.x << 6;
    int tid = threadIdx.x;
    int tx = tid & 15, ty = tid >> 4;
    __shared__ float As[16][68], Bs[16][68];
    float acc[4][4] = {};
    int lk = tid & 15, lr = tid >> 4;
    for (int k0 = 0; k0 < K; k0 += 16) {
        #pragma unroll
        for (int l = 0; l < 4; l++) {
            int m = lr + (l << 4);
            As[lk][m] = A[(long)(bm + m) * lda + k0 + lk];
            Bs[lk][m] = B[(long)(bn + m) * K   + k0 + lk];
        }
        __syncthreads();
        #pragma unroll
        for (int kk = 0; kk < 16; kk++) {
            float a[4], b[4];
            #pragma unroll
            for (int i = 0; i < 4; i++) { a[i] = As[kk][(ty<<2)+i]; b[i] = Bs[kk][(tx<<2)+i]; }
            #pragma unroll
            for (int i = 0; i < 4; i++)
                #pragma unroll
                for (int j = 0; j < 4; j++) acc[i][j] += a[i] * b[j];
        }
        __syncthreads();
    }
    #pragma unroll
    for (int i = 0; i < 4; i++) {
        int m = bm + (ty<<2) + i;
        #pragma unroll
        for (int j = 0; j < 4; j++) {
            int n = bn + (tx<<2) + j;
            float v = acc[i][j];
            if (bias) v += bias[n];
            C[(long)m * ldc + n] = v;
        }
    }
}

// ---------------- per-(scale,head,node) attention scalars ----------------
__global__ void k_scores(const float* al_s, const float* al_d,
                         const float* am_s, const float* am_d,
                         const float* ag_s, const float* ag_d) {
    int item = blockIdx.x * 8 + (threadIdx.x >> 5);
    int lane = threadIdx.x & 31;
    if (item >= 3*HH*NN) return;
    int n  = item & (NN - 1);
    int hh = item >> 12;            // sc*4 + h
    int sc = hh >> 2, h = hh & 3;
    const float* as = sc == 0 ? al_s : (sc == 1 ? am_s : ag_s);
    const float* ad = sc == 0 ? al_d : (sc == 1 ? am_d : ag_d);
    const float* zr = g_z + ((long)hh * NN + n) * DD;
    float s1 = 0.f, s2 = 0.f;
    for (int d0 = lane; d0 < DD; d0 += 32) {
        float zv = zr[d0];
        s1 += zv * as[h*DD + d0];
        s2 += zv * ad[h*DD + d0];
    }
    #pragma unroll
    for (int o = 16; o; o >>= 1) {
        s1 += __shfl_down_sync(0xffffffffu, s1, o);
        s2 += __shfl_down_sync(0xffffffffu, s2, o);
    }
    if (lane == 0) {
        g_ssrc[item] = s1; g_F1[item] = expf(s1);  g_F2[item] = expf(0.2f * s1);
        g_T[item] = -s2;   g_E1[item] = expf(s2);  g_E2[item] = expf(0.2f * s2);
    }
}

// ---------------- masked sparse GAT aggregation (local & mid) ----------------
__global__ void k_agg(int sc, const unsigned* __restrict__ M,
                      const float* __restrict__ bias,
                      float* __restrict__ out, int ldo) {
    int i = blockIdx.x, tid = threadIdx.x;    // 256 threads
    __shared__ int   s_idx[NN];
    __shared__ float s_w[64][4];
    __shared__ int   s_cntw[NW], s_off[NW + 1];
    __shared__ float s_t[4], s_e1[4], s_e2[4];
    if (tid < 4) {
        int id = (sc*4 + tid) * NN + i;
        s_t[tid] = g_T[id]; s_e1[tid] = g_E1[id]; s_e2[tid] = g_E2[id];
    }
    if (tid < NW) s_cntw[tid] = __popc(M[i*NW + tid]);
    __syncthreads();
    if (tid == 0) {                       // deterministic serial scan of 128 ints
        int a = 0;
        for (int w = 0; w < NW; w++) { s_off[w] = a; a += s_cntw[w]; }
        s_off[NW] = a;
    }
    __syncthreads();
    if (tid < NW) {
        unsigned bits = M[i*NW + tid];
        int p = s_off[tid];
        while (bits) { int b = __ffs(bits) - 1; bits &= bits - 1; s_idx[p++] = (tid<<5) + b; }
    }
    __syncthreads();
    int deg = s_off[NW];
    float acc[4] = {0,0,0,0}, den[4] = {0,0,0,0};
    int c = tid;
    for (int base = 0; base < deg; base += 64) {
        int cnt = min(64, deg - base);
        int jj = tid & 63, h = tid >> 6;
        if (jj < cnt) {
            int j = s_idx[base + jj];
            int id = (sc*4 + h) * NN + j;
            float sj = g_ssrc[id];
            float w = (sj > s_t[h]) ? s_e1[h] * g_F1[id] : s_e2[h] * g_F2[id];
            s_w[jj][h] = w;
        }
        __syncthreads();
        for (int q = 0; q < cnt; q++) {
            int j = s_idx[base + q];
            const float* zp = g_z + ((long)(sc*4) * NN + j) * DD + c;
            #pragma unroll
            for (int h2 = 0; h2 < 4; h2++) {
                float w = s_w[q][h2];
                den[h2] += w;
                acc[h2] += w * zp[(long)h2 * NN * DD];
            }
        }
        __syncthreads();
    }
    float m = 0.f;
    #pragma unroll
    for (int h2 = 0; h2 < 4; h2++) m += acc[h2] / den[h2];
    m = 0.25f * m + bias[c];
    out[(long)i * ldo + c] = fmaxf(m, 0.f);
}

// ---------------- global scale: sort + prefix + combine ----------------
__global__ void k_sort() {     // one block per head, 1024 threads
    int h = blockIdx.x, tid = threadIdx.x;
    __shared__ float key[NN];
    __shared__ int   idx[NN];
    for (int i = tid; i < NN; i += 1024) { key[i] = g_ssrc[(8 + h)*NN + i]; idx[i] = i; }
    __syncthreads();
    for (int k = 2; k <= NN; k <<= 1) {
        for (int j = k >> 1; j > 0; j >>= 1) {
            for (int i = tid; i < NN; i += 1024) {
                int ixj = i ^ j;
                if (ixj > i) {
                    bool up = (i & k) == 0;
                    float a = key[i], b = key[ixj];
                    if ((a > b) == up) {
                        key[i] = b; key[ixj] = a;
                        int t = idx[i]; idx[i] = idx[ixj]; idx[ixj] = t;
                    }
                }
            }
            __syncthreads();
        }
    }
    for (int i = tid; i < NN; i += 1024) { g_sorted[h*NN + i] = key[i]; g_perm[h*NN + i] = idx[i]; }
}

__global__ void k_prefix() {   // one block per head, 256 threads (one per channel)
    int h = blockIdx.x, c = threadIdx.x;
    float a1 = 0.f, a2 = 0.f;
    const int base = (8 + h) * NN;
    for (int r = 0; r < NN; r++) {
        int j = g_perm[h*NN + r];
        float f1 = g_F1[base + j], f2 = g_F2[base + j];
        float zv = g_z[((long)base + j) * DD + c];
        a1 += f1 * zv; a2 += f2 * zv;
        g_P1[((long)h*NN + r)*DD + c] = a1;
        g_P2[((long)h*NN + r)*DD + c] = a2;
    }
}

__global__ void k_prefix_scalar() {  // one block per head
    int h = blockIdx.x, tid = threadIdx.x;
    __shared__ float f1s[NN], f2s[NN];
    int base = (8 + h) * NN;
    for (int i = tid; i < NN; i += blockDim.x) {
        int j = g_perm[h*NN + i];
        f1s[i] = g_F1[base + j]; f2s[i] = g_F2[base + j];
    }
    __syncthreads();
    if (tid == 0) {
        float a1 = 0.f, a2 = 0.f;
        for (int r = 0; r < NN; r++) {
            a1 += f1s[r]; a2 += f2s[r];
            g_C1[h*NN + r] = a1; g_C2[h*NN + r] = a2;
        }
    }
}

__global__ void k_global(const float* __restrict__ bias) {
    int i = blockIdx.x, tid = threadIdx.x;  // 256 threads
    __shared__ int   s_r[4];
    __shared__ float s_den[4], s_e1[4], s_e2[4];
    if (tid < 4) {
        int h = tid, id = (8 + h)*NN + i;
        float t = g_T[id], e1 = g_E1[id], e2 = g_E2[id];
        const float* key = g_sorted + h*NN;
        int lo = 0, hi = NN;
        while (lo < hi) { int mid = (lo + hi) >> 1; if (key[mid] <= t) lo = mid + 1; else hi = mid; }
        int r = lo;                                       // count of s_j <= t
        float c1 = r ? g_C1[h*NN + r - 1] : 0.f;
        float c2 = r ? g_C2[h*NN + r - 1] : 0.f;
        float c1t = g_C1[h*NN + NN - 1];
        s_r[h] = r; s_e1[h] = e1; s_e2[h] = e2;
        s_den[h] = e1 * (c1t - c1) + e2 * c2;
    }
    __syncthreads();
    int c = tid; float m = 0.f;
    #pragma unroll
    for (int h = 0; h < 4; h++) {
        int r = s_r[h];
        long pb = (long)h * NN * DD;
        float p1 = r ? g_P1[pb + (long)(r-1)*DD + c] : 0.f;
        float p2 = r ? g_P2[pb + (long)(r-1)*DD + c] : 0.f;
        float t1 = g_P1[pb + (long)(NN-1)*DD + c];
        float num = s_e1[h] * (t1 - p1) + s_e2[h] * p2;
        m += num / s_den[h];
    }
    m = 0.25f * m + bias[c];
    g_cat[(long)i*768 + 512 + c] = fmaxf(m, 0.f);
}

// ---------------- 3-way scale attention (MHA core) ----------------
__global__ void k_attn() {
    int n = blockIdx.x, tid = threadIdx.x;  // 128 threads = 4 warps = 4 heads
    int h = tid >> 5, lane = tid & 31;
    const float* qp = g_q + (long)n*DD + h*DHH;
    float s[3];
    #pragma unroll
    for (int sc = 0; sc < 3; sc++) {
        const float* kp = g_k3 + ((long)sc*NN + n)*DD + h*DHH;
        float acc = qp[lane]*kp[lane] + qp[lane+32]*kp[lane+32];
        #pragma unroll
        for (int o = 16; o; o >>= 1) acc += __shfl_xor_sync(0xffffffffu, acc, o);
        s[sc] = acc * 0.125f;                 // 1/sqrt(64)
    }
    float mx = fmaxf(s[0], fmaxf(s[1], s[2]));
    float e0 = expf(s[0]-mx), e1 = expf(s[1]-mx), e2 = expf(s[2]-mx);
    float inv = 1.f / (e0 + e1 + e2);
    e0 *= inv; e1 *= inv; e2 *= inv;
    #pragma unroll
    for (int p = 0; p < 2; p++) {
        int d0 = h*DHH + lane + p*32;
        long off = (long)n*DD + d0;
        g_att[off] = e0*g_v3[off] + e1*g_v3[(long)NN*DD + off] + e2*g_v3[2L*NN*DD + off];
    }
}

// ---------------- fusion LayerNorm + ReLU + residual add ----------------
__global__ void k_final(const float* __restrict__ lng, const float* __restrict__ lnb,
                        float* __restrict__ out) {
    int i = blockIdx.x, c = threadIdx.x;  // 256
    __shared__ float red[256];
    float v = g_hbuf[(long)i*DD + c];
    red[c] = v; __syncthreads();
    #pragma unroll
    for (int o = 128; o; o >>= 1) { if (c < o) red[c] += red[c+o]; __syncthreads(); }
    float mu = red[0] * (1.f / DD);
    __syncthreads();
    float dv = v - mu;
    red[c] = dv * dv; __syncthreads();
    #pragma unroll
    for (int o = 128; o; o >>= 1) { if (c < o) red[c] += red[c+o]; __syncthreads(); }
    float var = red[0] * (1.f / DD);
    float y = dv * rsqrtf(var + LNEPS) * lng[c] + lnb[c];
    y = fmaxf(y, 0.f);
    out[(long)i*DD + c] = y + g_xatt[(long)i*DD + c];
}

// ---------------- launch ----------------
extern "C" void kernel_launch(void* const* d_in, const int* in_sizes, int n_in,
                              void* d_out, int out_size) {
    const float* x    = (const float*)d_in[0];
    const int*   edges= (const int*)  d_in[1];
    const float* Wl   = (const float*)d_in[2];
    const float* als  = (const float*)d_in[3];
    const float* ald  = (const float*)d_in[4];
    const float* bl   = (const float*)d_in[5];
    const float* Wm   = (const float*)d_in[6];
    const float* ams  = (const float*)d_in[7];
    const float* amd  = (const float*)d_in[8];
    const float* bm   = (const float*)d_in[9];
    const float* Wg   = (const float*)d_in[10];
    const float* ags  = (const float*)d_in[11];
    const float* agd  = (const float*)d_in[12];
    const float* bg   = (const float*)d_in[13];
    const float* Wq   = (const float*)d_in[14];
    const float* bq   = (const float*)d_in[15];
    const float* Wk   = (const float*)d_in[16];
    const float* bk   = (const float*)d_in[17];
    const float* Wv   = (const float*)d_in[18];
    const float* bv   = (const float*)d_in[19];
    const float* Wo   = (const float*)d_in[20];
    const float* bo   = (const float*)d_in[21];
    const float* Wf   = (const float*)d_in[22];
    const float* bfv  = (const float*)d_in[23];
    const float* lng  = (const float*)d_in[24];
    const float* lnb  = (const float*)d_in[25];
    float* out = (float*)d_out;

    float* zbase; cudaGetSymbolAddress((void**)&zbase, g_z);
    float* catp;  cudaGetSymbolAddress((void**)&catp,  g_cat);
    float* qp;    cudaGetSymbolAddress((void**)&qp,    g_q);
    float* kp;    cudaGetSymbolAddress((void**)&kp,    g_k3);
    float* vp;    cudaGetSymbolAddress((void**)&vp,    g_v3);
    float* attp;  cudaGetSymbolAddress((void**)&attp,  g_att);
    float* xattp; cudaGetSymbolAddress((void**)&xattp, g_xatt);
    float* hp;    cudaGetSymbolAddress((void**)&hp,    g_hbuf);
    unsigned* mlp; cudaGetSymbolAddress((void**)&mlp,  g_ML);
    unsigned* mmp; cudaGetSymbolAddress((void**)&mmp,  g_MM);

    k_detect<<<1, 32>>>((const unsigned*)edges);
    k_clear<<<(NN*NW + 255)/256, 256>>>();
    k_edges<<<(EE + 255)/256, 256>>>(edges);
    k_eye_ml<<<(NN + 255)/256, 256>>>();
    k_twohop<<<NN, NW>>>();
    k_mm<<<NN, NW>>>();

    // z projections: per scale, batched over 4 heads
    const float* Ws[3] = {Wl, Wm, Wg};
    for (int sc = 0; sc < 3; sc++)
        k_gemm<<<dim3(4, 64, 4), 256>>>(x, DD, 0,
                                        Ws[sc], (long)DD*DD, nullptr,
                                        zbase + (long)sc*4*NN*DD, DD, (long)NN*DD, DD);

    k_scores<<<(3*HH*NN)/8, 256>>>(als, ald, ams, amd, ags, agd);

    k_agg<<<NN, 256>>>(0, mlp, bl, catp + 0,   768);
    k_agg<<<NN, 256>>>(1, mmp, bm, catp + 256, 768);

    k_sort<<<HH, 1024>>>();
    k_prefix<<<HH, 256>>>();
    k_prefix_scalar<<<HH, 256>>>();
    k_global<<<NN, 256>>>(bg);

    // MHA projections
    k_gemm<<<dim3(4, 64, 1), 256>>>(x, DD, 0, Wq, 0, bq, qp, DD, 0, DD);
    k_gemm<<<dim3(4, 64, 3), 256>>>(catp, 768, 256, Wk, 0, bk, kp, DD, (long)NN*DD, DD);
    k_gemm<<<dim3(4, 64, 3), 256>>>(catp, 768, 256, Wv, 0, bv, vp, DD, (long)NN*DD, DD);
    k_attn<<<NN, 128>>>();
    k_gemm<<<dim3(4, 64, 1), 256>>>(attp, DD, 0, Wo, 0, bo, xattp, DD, 0, DD);

    // fusion MLP
    k_gemm<<<dim3(4, 64, 1), 256>>>(catp, 768, 0, Wf, 0, bfv, hp, DD, 0, 3*DD);
    k_final<<<NN, 256>>>(lng, lnb, out);
}

// round 2
// speedup vs baseline: 2.2363x; 2.2363x over previous
#include <cuda_runtime.h>
#include <math.h>
#include <stdint.h>

#define NN 4096
#define DD 256
#define HH 4
#define DHH 64
#define EE 65536
#define NW 128          // 4096 bits / 32
#define LNEPS 1e-5f

// ---------------- device scratch (static, no allocs) ----------------
__device__ int      g_is64;
__device__ unsigned g_A   [NN*NW];
__device__ unsigned g_ML  [NN*NW];
__device__ unsigned g_UND [NN*NW];
__device__ unsigned g_UNDT[NN*NW];
__device__ unsigned g_MM  [NN*NW];

// z layout: [sc][n][h*256+d]  (node-contiguous 1024-float rows)
__device__ float g_z   [3L*NN*HH*DD];
__device__ float g_ssrc[3*HH*NN];
__device__ float g_F1  [3*HH*NN];      // exp(ssrc)
__device__ float g_F2  [3*HH*NN];      // exp(0.2 ssrc)
__device__ float g_T   [3*HH*NN];      // -sdst
__device__ float g_E1  [3*HH*NN];      // exp(sdst)
__device__ float g_E2  [3*HH*NN];      // exp(0.2 sdst)

__device__ float g_cat [NN*3*DD];      // [x_local | x_mid | x_global], ld=768
__device__ float g_sorted[HH*NN];
__device__ int   g_perm  [HH*NN];
// chunk-local prefixes (128 rows per chunk, 32 chunks per head)
__device__ float g_P1[HH*NN*DD];
__device__ float g_P2[HH*NN*DD];
__device__ float g_C1[HH*NN];
__device__ float g_C2[HH*NN];
__device__ float g_T1[HH*32*DD], g_T2[HH*32*DD];   // chunk totals
__device__ float g_O1[HH*33*DD], g_O2[HH*33*DD];   // exclusive chunk offsets (+grand total)
__device__ float g_TC1[HH*32], g_TC2[HH*32];
__device__ float g_OC1[HH*33], g_OC2[HH*33];

__device__ float g_q   [NN*DD];
__device__ float g_k3  [3*NN*DD];
__device__ float g_v3  [3*NN*DD];
__device__ float g_att [NN*DD];
__device__ float g_xatt[NN*DD];
__device__ float g_hbuf[NN*DD];

// ---------------- small utility kernels ----------------
__global__ void k_detect(const unsigned* e) {
    if (threadIdx.x == 0) {
        int all0 = 1;
        for (int i = 0; i < 128; i++) if (e[2*i+1] != 0u) { all0 = 0; break; }
        g_is64 = all0;
    }
}

__global__ void k_clear() {
    int i = blockIdx.x * blockDim.x + threadIdx.x;
    if (i < NN*NW) { g_A[i] = 0u; g_ML[i] = 0u; }
}

__global__ void k_edges(const int* e) {
    int i = blockIdx.x * blockDim.x + threadIdx.x;
    if (i >= EE) return;
    int s, t;
    if (g_is64) { s = e[2*i]; t = e[2*(EE+i)]; }
    else        { s = e[i];   t = e[EE+i];     }
    atomicOr(&g_A [s*NW + (t>>5)], 1u << (t & 31));   // A[s][t]
    atomicOr(&g_ML[t*NW + (s>>5)], 1u << (s & 31));   // M_local = A^T
}

__global__ void k_eye_ml() {
    int i = blockIdx.x * blockDim.x + threadIdx.x;
    if (i < NN) g_ML[i*NW + (i>>5)] |= 1u << (i & 31);
}

// und[i] = A[i] | OR_{k in out(i)} A[k]
__global__ void k_twohop() {
    int i = blockIdx.x, w = threadIdx.x;   // 128 threads
    __shared__ unsigned sh[NW];
    sh[w] = g_A[i*NW + w];
    __syncthreads();
    unsigned acc = sh[w];
    for (int w2 = 0; w2 < NW; w2++) {
        unsigned bits = sh[w2];
        while (bits) {
            int b = __ffs(bits) - 1; bits &= bits - 1;
            acc |= g_A[((w2<<5)+b)*NW + w];
        }
    }
    g_UND[i*NW + w] = acc;
}

// bit-transpose UND -> UNDT (32x32 tiles, 8 tiles per 256-thread block)
__global__ void k_transpose() {
    int tile = blockIdx.x * 8 + (threadIdx.x >> 5);   // 0..16383
    int lane = threadIdx.x & 31;
    int ti = tile >> 7, tj = tile & 127;
    __shared__ unsigned sm[8][32];
    int wslot = threadIdx.x >> 5;
    sm[wslot][lane] = g_UND[(ti*32 + lane)*NW + tj];
    __syncwarp();
    unsigned y = 0;
    #pragma unroll
    for (int b = 0; b < 32; b++) y |= ((sm[wslot][b] >> lane) & 1u) << b;
    g_UNDT[(tj*32 + lane)*NW + ti] = y;
}

// MM[i] = UND[i] | UNDT[i] | eye
__global__ void k_mm() {
    int i = blockIdx.x, w = threadIdx.x;   // 128 threads
    unsigned res = g_UND[i*NW + w] | g_UNDT[i*NW + w];
    if (w == (i >> 5)) res |= 1u << (i & 31);
    g_MM[i*NW + w] = res;
}

// ---------------- generic C[M,256] = A[M,K] @ B[256,K]^T (+bias) ----------------
__global__ void k_gemm(const float* __restrict__ A, int lda, long sA,
                       const float* __restrict__ B, long sB,
                       const float* __restrict__ bias,
                       float* __restrict__ C, int ldc, long sC, int K) {
    int bz = blockIdx.z;
    A += (long)bz * sA; B += (long)bz * sB; C += (long)bz * sC;
    int bm = blockIdx.y << 6, bn = blockIdx.x << 6;
    int tid = threadIdx.x;
    int tx = tid & 15, ty = tid >> 4;
    __shared__ float As[16][68], Bs[16][68];
    float acc[4][4] = {};
    int lk = tid & 15, lr = tid >> 4;
    for (int k0 = 0; k0 < K; k0 += 16) {
        #pragma unroll
        for (int l = 0; l < 4; l++) {
            int m = lr + (l << 4);
            As[lk][m] = A[(long)(bm + m) * lda + k0 + lk];
            Bs[lk][m] = B[(long)(bn + m) * K   + k0 + lk];
        }
        __syncthreads();
        #pragma unroll
        for (int kk = 0; kk < 16; kk++) {
            float a[4], b[4];
            #pragma unroll
            for (int i = 0; i < 4; i++) { a[i] = As[kk][(ty<<2)+i]; b[i] = Bs[kk][(tx<<2)+i]; }
            #pragma unroll
            for (int i = 0; i < 4; i++)
                #pragma unroll
                for (int j = 0; j < 4; j++) acc[i][j] += a[i] * b[j];
        }
        __syncthreads();
    }
    #pragma unroll
    for (int i = 0; i < 4; i++) {
        int m = bm + (ty<<2) + i;
        #pragma unroll
        for (int j = 0; j < 4; j++) {
            int n = bn + (tx<<2) + j;
            float v = acc[i][j];
            if (bias) v += bias[n];
            C[(long)m * ldc + n] = v;
        }
    }
}

// ---------------- per-(scale,head,node) attention scalars ----------------
__global__ void k_scores(const float* al_s, const float* al_d,
                         const float* am_s, const float* am_d,
                         const float* ag_s, const float* ag_d) {
    int item = blockIdx.x * 8 + (threadIdx.x >> 5);
    int lane = threadIdx.x & 31;
    if (item >= 3*HH*NN) return;
    int n  = item & (NN - 1);
    int hh = item >> 12;            // sc*4 + h
    int sc = hh >> 2, h = hh & 3;
    const float* as = sc == 0 ? al_s : (sc == 1 ? am_s : ag_s);
    const float* ad = sc == 0 ? al_d : (sc == 1 ? am_d : ag_d);
    const float* zr = g_z + ((long)sc*NN + n)*1024 + h*DD;
    float s1 = 0.f, s2 = 0.f;
    for (int d0 = lane; d0 < DD; d0 += 32) {
        float zv = zr[d0];
        s1 += zv * as[h*DD + d0];
        s2 += zv * ad[h*DD + d0];
    }
    #pragma unroll
    for (int o = 16; o; o >>= 1) {
        s1 += __shfl_down_sync(0xffffffffu, s1, o);
        s2 += __shfl_down_sync(0xffffffffu, s2, o);
    }
    if (lane == 0) {
        g_ssrc[item] = s1; g_F1[item] = expf(s1);  g_F2[item] = expf(0.2f * s1);
        g_T[item] = -s2;   g_E1[item] = expf(s2);  g_E2[item] = expf(0.2f * s2);
    }
}

// ---------------- masked sparse GAT aggregation (local & mid) ----------------
__global__ void k_agg(int sc, const unsigned* __restrict__ M,
                      const float* __restrict__ bias,
                      float* __restrict__ out, int ldo) {
    int i = blockIdx.x, tid = threadIdx.x;    // 256 threads
    __shared__ int   s_idx[NN];
    __shared__ float s_w[64][4];
    __shared__ float s_cmb[1024];
    __shared__ int   s_cntw[NW], s_off[NW + 1];
    __shared__ float s_t[4], s_e1[4], s_e2[4];
    if (tid < 4) {
        int id = (sc*4 + tid) * NN + i;
        s_t[tid] = g_T[id]; s_e1[tid] = g_E1[id]; s_e2[tid] = g_E2[id];
    }
    if (tid < NW) s_cntw[tid] = __popc(M[i*NW + tid]);
    __syncthreads();
    if (tid == 0) {
        int a = 0;
        for (int w = 0; w < NW; w++) { s_off[w] = a; a += s_cntw[w]; }
        s_off[NW] = a;
    }
    __syncthreads();
    if (tid < NW) {
        unsigned bits = M[i*NW + tid];
        int p = s_off[tid];
        while (bits) { int b = __ffs(bits) - 1; bits &= bits - 1; s_idx[p++] = (tid<<5) + b; }
    }
    __syncthreads();
    int deg = s_off[NW];
    int h = tid >> 6;
    const float4* zb = (const float4*)(g_z + (long)sc*NN*1024);
    float4 acc = make_float4(0.f,0.f,0.f,0.f);
    float den = 0.f;
    for (int base = 0; base < deg; base += 64) {
        int cnt = min(64, deg - base);
        int jj = tid & 63;
        if (jj < cnt) {
            int j = s_idx[base + jj];
            int id = (sc*4 + h) * NN + j;
            float sj = g_ssrc[id];
            s_w[jj][h] = (sj > s_t[h]) ? s_e1[h] * g_F1[id] : s_e2[h] * g_F2[id];
        }
        __syncthreads();
        for (int q = 0; q < cnt; q++) {
            int j = s_idx[base + q];
            float4 zv = zb[(long)j * 256 + tid];
            float w = s_w[q][h];
            den += w;
            acc.x += w * zv.x; acc.y += w * zv.y;
            acc.z += w * zv.z; acc.w += w * zv.w;
        }
        __syncthreads();
    }
    float inv = 0.25f / den;
    ((float4*)s_cmb)[tid] = make_float4(acc.x*inv, acc.y*inv, acc.z*inv, acc.w*inv);
    __syncthreads();
    int c = tid;
    float m = s_cmb[c] + s_cmb[256+c] + s_cmb[512+c] + s_cmb[768+c];
    out[(long)i * ldo + c] = fmaxf(m + bias[c], 0.f);
}

// ---------------- global scale: sort + chunked prefix + combine ----------------
__global__ void k_sort() {     // one block per head, 1024 threads
    int h = blockIdx.x, tid = threadIdx.x;
    __shared__ float key[NN];
    __shared__ int   idx[NN];
    for (int i = tid; i < NN; i += 1024) { key[i] = g_ssrc[(8 + h)*NN + i]; idx[i] = i; }
    __syncthreads();
    for (int k = 2; k <= NN; k <<= 1) {
        for (int j = k >> 1; j > 0; j >>= 1) {
            for (int i = tid; i < NN; i += 1024) {
                int ixj = i ^ j;
                if (ixj > i) {
                    bool up = (i & k) == 0;
                    float a = key[i], b = key[ixj];
                    if ((a > b) == up) {
                        key[i] = b; key[ixj] = a;
                        int t = idx[i]; idx[i] = idx[ixj]; idx[ixj] = t;
                    }
                }
            }
            __syncthreads();
        }
    }
    for (int i = tid; i < NN; i += 1024) { g_sorted[h*NN + i] = key[i]; g_perm[h*NN + i] = idx[i]; }
}

// Phase A: chunk-local prefix (128 rows per chunk), 128 blocks of 256 threads
__global__ void k_prefA() {
    int h = blockIdx.x >> 5, k = blockIdx.x & 31;
    int c = threadIdx.x;
    int base = (8 + h) * NN;
    float a1 = 0.f, a2 = 0.f, c1 = 0.f, c2 = 0.f;
    int r0 = k << 7;
    for (int l = 0; l < 128; l++) {
        int r = r0 + l;
        int j = g_perm[h*NN + r];
        float f1 = g_F1[base + j], f2 = g_F2[base + j];
        float zv = g_z[((long)2*NN + j)*1024 + h*DD + c];
        a1 += f1 * zv; a2 += f2 * zv;
        g_P1[((long)h*NN + r)*DD + c] = a1;
        g_P2[((long)h*NN + r)*DD + c] = a2;
        if (c == 0) { c1 += f1; c2 += f2; g_C1[h*NN + r] = c1; g_C2[h*NN + r] = c2; }
    }
    g_T1[(h*32 + k)*DD + c] = a1;
    g_T2[(h*32 + k)*DD + c] = a2;
    if (c == 0) { g_TC1[h*32 + k] = c1; g_TC2[h*32 + k] = c2; }
}

// Phase B: exclusive scan of chunk totals (33rd entry = grand total)
__global__ void k_prefB() {
    int h = blockIdx.x, c = threadIdx.x;
    float o1 = 0.f, o2 = 0.f;
    for (int k = 0; k < 32; k++) {
        g_O1[(h*33 + k)*DD + c] = o1; g_O2[(h*33 + k)*DD + c] = o2;
        o1 += g_T1[(h*32 + k)*DD + c]; o2 += g_T2[(h*32 + k)*DD + c];
    }
    g_O1[(h*33 + 32)*DD + c] = o1; g_O2[(h*33 + 32)*DD + c] = o2;
    if (c == 0) {
        float oc1 = 0.f, oc2 = 0.f;
        for (int k = 0; k < 32; k++) {
            g_OC1[h*33 + k] = oc1; g_OC2[h*33 + k] = oc2;
            oc1 += g_TC1[h*32 + k]; oc2 += g_TC2[h*32 + k];
        }
        g_OC1[h*33 + 32] = oc1; g_OC2[h*33 + 32] = oc2;
    }
}

__global__ void k_global(const float* __restrict__ bias) {
    int i = blockIdx.x, tid = threadIdx.x;  // 256 threads
    __shared__ int   s_r[4], s_kc[4];
    __shared__ float s_den[4], s_e1[4], s_e2[4];
    if (tid < 4) {
        int h = tid, id = (8 + h)*NN + i;
        float t = g_T[id], e1 = g_E1[id], e2 = g_E2[id];
        const float* key = g_sorted + h*NN;
        int lo = 0, hi = NN;
        while (lo < hi) { int mid = (lo + hi) >> 1; if (key[mid] <= t) lo = mid + 1; else hi = mid; }
        int r = lo;                                       // count of s_j <= t
        float c1 = 0.f, c2 = 0.f; int kc = 0;
        if (r) {
            int idx = r - 1; kc = idx >> 7;
            c1 = g_C1[h*NN + idx] + g_OC1[h*33 + kc];
            c2 = g_C2[h*NN + idx] + g_OC2[h*33 + kc];
        }
        float c1t = g_OC1[h*33 + 32];
        s_r[h] = r; s_kc[h] = kc; s_e1[h] = e1; s_e2[h] = e2;
        s_den[h] = e1 * (c1t - c1) + e2 * c2;
    }
    __syncthreads();
    int c = tid; float m = 0.f;
    #pragma unroll
    for (int h = 0; h < 4; h++) {
        int r = s_r[h];
        float p1 = 0.f, p2 = 0.f;
        if (r) {
            int idx = r - 1, kc = s_kc[h];
            p1 = g_P1[((long)h*NN + idx)*DD + c] + g_O1[(h*33 + kc)*DD + c];
            p2 = g_P2[((long)h*NN + idx)*DD + c] + g_O2[(h*33 + kc)*DD + c];
        }
        float t1 = g_O1[(h*33 + 32)*DD + c];
        float num = s_e1[h] * (t1 - p1) + s_e2[h] * p2;
        m += num / s_den[h];
    }
    m = 0.25f * m + bias[c];
    g_cat[(long)i*768 + 512 + c] = fmaxf(m, 0.f);
}

// ---------------- 3-way scale attention (MHA core) ----------------
__global__ void k_attn() {
    int n = blockIdx.x, tid = threadIdx.x;  // 128 threads = 4 warps = 4 heads
    int h = tid >> 5, lane = tid & 31;
    const float* qp = g_q + (long)n*DD + h*DHH;
    float s[3];
    #pragma unroll
    for (int sc = 0; sc < 3; sc++) {
        const float* kp = g_k3 + ((long)sc*NN + n)*DD + h*DHH;
        float acc = qp[lane]*kp[lane] + qp[lane+32]*kp[lane+32];
        #pragma unroll
        for (int o = 16; o; o >>= 1) acc += __shfl_xor_sync(0xffffffffu, acc, o);
        s[sc] = acc * 0.125f;
    }
    float mx = fmaxf(s[0], fmaxf(s[1], s[2]));
    float e0 = expf(s[0]-mx), e1 = expf(s[1]-mx), e2 = expf(s[2]-mx);
    float inv = 1.f / (e0 + e1 + e2);
    e0 *= inv; e1 *= inv; e2 *= inv;
    #pragma unroll
    for (int p = 0; p < 2; p++) {
        int d0 = h*DHH + lane + p*32;
        long off = (long)n*DD + d0;
        g_att[off] = e0*g_v3[off] + e1*g_v3[(long)NN*DD + off] + e2*g_v3[2L*NN*DD + off];
    }
}

// ---------------- fusion LayerNorm + ReLU + residual add ----------------
__global__ void k_final(const float* __restrict__ lng, const float* __restrict__ lnb,
                        float* __restrict__ out) {
    int i = blockIdx.x, c = threadIdx.x;  // 256
    __shared__ float red[256];
    float v = g_hbuf[(long)i*DD + c];
    red[c] = v; __syncthreads();
    #pragma unroll
    for (int o = 128; o; o >>= 1) { if (c < o) red[c] += red[c+o]; __syncthreads(); }
    float mu = red[0] * (1.f / DD);
    __syncthreads();
    float dv = v - mu;
    red[c] = dv * dv; __syncthreads();
    #pragma unroll
    for (int o = 128; o; o >>= 1) { if (c < o) red[c] += red[c+o]; __syncthreads(); }
    float var = red[0] * (1.f / DD);
    float y = dv * rsqrtf(var + LNEPS) * lng[c] + lnb[c];
    y = fmaxf(y, 0.f);
    out[(long)i*DD + c] = y + g_xatt[(long)i*DD + c];
}

// ---------------- launch ----------------
extern "C" void kernel_launch(void* const* d_in, const int* in_sizes, int n_in,
                              void* d_out, int out_size) {
    const float* x    = (const float*)d_in[0];
    const int*   edges= (const int*)  d_in[1];
    const float* Wl   = (const float*)d_in[2];
    const float* als  = (const float*)d_in[3];
    const float* ald  = (const float*)d_in[4];
    const float* bl   = (const float*)d_in[5];
    const float* Wm   = (const float*)d_in[6];
    const float* ams  = (const float*)d_in[7];
    const float* amd  = (const float*)d_in[8];
    const float* bm   = (const float*)d_in[9];
    const float* Wg   = (const float*)d_in[10];
    const float* ags  = (const float*)d_in[11];
    const float* agd  = (const float*)d_in[12];
    const float* bg   = (const float*)d_in[13];
    const float* Wq   = (const float*)d_in[14];
    const float* bq   = (const float*)d_in[15];
    const float* Wk   = (const float*)d_in[16];
    const float* bk   = (const float*)d_in[17];
    const float* Wv   = (const float*)d_in[18];
    const float* bv   = (const float*)d_in[19];
    const float* Wo   = (const float*)d_in[20];
    const float* bo   = (const float*)d_in[21];
    const float* Wf   = (const float*)d_in[22];
    const float* bfv  = (const float*)d_in[23];
    const float* lng  = (const float*)d_in[24];
    const float* lnb  = (const float*)d_in[25];
    float* out = (float*)d_out;

    float* zbase; cudaGetSymbolAddress((void**)&zbase, g_z);
    float* catp;  cudaGetSymbolAddress((void**)&catp,  g_cat);
    float* qp;    cudaGetSymbolAddress((void**)&qp,    g_q);
    float* kp;    cudaGetSymbolAddress((void**)&kp,    g_k3);
    float* vp;    cudaGetSymbolAddress((void**)&vp,    g_v3);
    float* attp;  cudaGetSymbolAddress((void**)&attp,  g_att);
    float* xattp; cudaGetSymbolAddress((void**)&xattp, g_xatt);
    float* hp;    cudaGetSymbolAddress((void**)&hp,    g_hbuf);
    unsigned* mlp; cudaGetSymbolAddress((void**)&mlp,  g_ML);
    unsigned* mmp; cudaGetSymbolAddress((void**)&mmp,  g_MM);

    k_detect<<<1, 32>>>((const unsigned*)edges);
    k_clear<<<(NN*NW + 255)/256, 256>>>();
    k_edges<<<(EE + 255)/256, 256>>>(edges);
    k_eye_ml<<<(NN + 255)/256, 256>>>();
    k_twohop<<<NN, NW>>>();
    k_transpose<<<2048, 256>>>();
    k_mm<<<NN, NW>>>();

    // z projections: per scale, batched over 4 heads; z row layout [n][h*256+d]
    const float* Ws[3] = {Wl, Wm, Wg};
    for (int sc = 0; sc < 3; sc++)
        k_gemm<<<dim3(4, 64, 4), 256>>>(x, DD, 0,
                                        Ws[sc], (long)DD*DD, nullptr,
                                        zbase + (long)sc*NN*1024, 1024, 256, DD);

    k_scores<<<(3*HH*NN)/8, 256>>>(als, ald, ams, amd, ags, agd);

    k_agg<<<NN, 256>>>(0, mlp, bl, catp + 0,   768);
    k_agg<<<NN, 256>>>(1, mmp, bm, catp + 256, 768);

    k_sort<<<HH, 1024>>>();
    k_prefA<<<HH*32, 256>>>();
    k_prefB<<<HH, 256>>>();
    k_global<<<NN, 256>>>(bg);

    // MHA projections
    k_gemm<<<dim3(4, 64, 1), 256>>>(x, DD, 0, Wq, 0, bq, qp, DD, 0, DD);
    k_gemm<<<dim3(4, 64, 3), 256>>>(catp, 768, 256, Wk, 0, bk, kp, DD, (long)NN*DD, DD);
    k_gemm<<<dim3(4, 64, 3), 256>>>(catp, 768, 256, Wv, 0, bv, vp, DD, (long)NN*DD, DD);
    k_attn<<<NN, 128>>>();
    k_gemm<<<dim3(4, 64, 1), 256>>>(attp, DD, 0, Wo, 0, bo, xattp, DD, 0, DD);

    // fusion MLP
    k_gemm<<<dim3(4, 64, 1), 256>>>(catp, 768, 0, Wf, 0, bfv, hp, DD, 0, 3*DD);
    k_final<<<NN, 256>>>(lng, lnb, out);
}